// round 3
// baseline (speedup 1.0000x reference)
#include <cuda_runtime.h>
#include <math.h>
#include <float.h>
#include <string.h>

// Problem constants
#define BB 32
#define NN 4096
#define CC 1024
#define CRR 256
#define HH 16
#define HDD 16
#define SCALE 0.25f          // HD^-0.5
#define NTILES 8
#define XSTR 66              // K3 smem row stride in float2 units (64 tokens + pad)
#define WKSTR 260            // K2 padded Wk tile row stride (floats)

typedef unsigned long long ull;

union F4U2 { float4 f; ull u[2]; };

__device__ __forceinline__ void fma2(ull& d, ull a, ull b) {
    asm("fma.rn.f32x2 %0, %1, %2, %0;" : "+l"(d) : "l"(a), "l"(b));
}

// ---------------- device scratch ----------------
__device__ float d_q[BB * CRR];
__device__ float d_w[BB * HH * CC];
__device__ float d_logits[BB * HH * NN];
__device__ float d_yp[NTILES * BB * HH * CC];

// ---------------- K1: q[b,r] = (x[b,0,:] @ Wq[:,r]) * SCALE ----------------
__global__ void qproj_kernel(const float* __restrict__ x, const float* __restrict__ Wq) {
    __shared__ float x0[CC];
    int b = blockIdx.x, tid = threadIdx.x;
    const float* xb = x + (size_t)b * NN * CC;
    for (int i = tid; i < CC; i += 256) x0[i] = xb[i];
    __syncthreads();
    float acc = 0.f;
#pragma unroll 8
    for (int c = 0; c < CC; c++) acc += x0[c] * Wq[c * CRR + tid];
    d_q[b * CRR + tid] = acc * SCALE;
}

// ---------------- K2: w[b,h,c] = sum_d Wk[c, h*16+d] * q[b, h*16+d] ----------------
// grid 16 (64-row c blocks), 256 threads. Padded Wk tile (stride 260) kills the
// 8-way bank conflict the unpadded stride-256 layout had.
__global__ void wk_kernel(const float* __restrict__ Wk) {
    extern __shared__ float sm[];
    float* Wks = sm;                   // [64][WKSTR]
    float* qs  = sm + 64 * WKSTR;      // [32][256]
    int tid = threadIdx.x;
    int c0 = blockIdx.x * 64;
    for (int i = tid; i < 64 * 256; i += 256)
        Wks[(i >> 8) * WKSTR + (i & 255)] = Wk[c0 * 256 + i];
    for (int i = tid; i < BB * CRR; i += 256) qs[i] = d_q[i];
    __syncthreads();
    int rl = tid >> 2;          // local row 0..63
    int hg = tid & 3;           // head group 0..3
    for (int b = 0; b < BB; b++) {
#pragma unroll
        for (int k = 0; k < 4; k++) {
            int h = hg * 4 + k;
            float acc = 0.f;
#pragma unroll
            for (int d = 0; d < HDD; d++)
                acc += Wks[rl * WKSTR + h * 16 + d] * qs[b * 256 + h * 16 + d];
            d_w[((size_t)b * HH + h) * CC + c0 + rl] = acc;
        }
    }
}

// ---------------- K3: logits[b,h,n] = x[b,n,:] . w[b,h,:]  (f32x2 channel-paired) ----
// 256 threads = 8 warps, warp owns 64 tokens (2/lane). grid (32, 8).
// smem: ws[16][1024] (64 KB) + per-warp x tile [8 c2][XSTR] float2 (~33 KB).
// ~97 KB total -> 2 blocks/SM, 16 warps/SM.
__global__ __launch_bounds__(256, 2) void logits_kernel(const float* __restrict__ x) {
    extern __shared__ float sm[];
    float* ws = sm;                                        // 16*1024 floats
    int tid = threadIdx.x, lane = tid & 31, warp = tid >> 5;
    float2* xs2 = (float2*)(sm + HH * CC) + warp * (8 * XSTR);
    int b = blockIdx.x;
    const float* wb = d_w + (size_t)b * HH * CC;
    for (int i = tid; i < (HH * CC) / 4; i += 256)
        ((float4*)ws)[i] = ((const float4*)wb)[i];
    __syncthreads();

    int n0 = blockIdx.y * 512 + warp * 64;
    const float* xb = x + ((size_t)b * NN + n0) * CC;

    ull acc[16][2];
#pragma unroll
    for (int h = 0; h < 16; h++) { acc[h][0] = 0ull; acc[h][1] = 0ull; }

    for (int cb = 0; cb < CC; cb += 16) {
        // stage 64 tokens x 16 channels, as channel-pair float2s [c2][t]
#pragma unroll
        for (int i = 0; i < 8; i++) {
            int linear = lane + 32 * i;      // 0..255
            int t  = linear >> 2;            // 0..63
            int c2 = (linear & 3) * 2;       // 0,2,4,6
            F4U2 v; v.f = *(const float4*)(xb + (size_t)t * CC + cb + c2 * 2);
            xs2[(c2 + 0) * XSTR + t] = make_float2(v.f.x, v.f.y);
            xs2[(c2 + 1) * XSTR + t] = make_float2(v.f.z, v.f.w);
        }
        __syncwarp();

#pragma unroll
        for (int c2p = 0; c2p < 8; c2p += 2) {
            ull xa[2][2];
#pragma unroll
            for (int k = 0; k < 2; k++) {
                float2 v0 = xs2[(c2p + 0) * XSTR + lane + 32 * k];
                float2 v1 = xs2[(c2p + 1) * XSTR + lane + 32 * k];
                xa[k][0] = *(ull*)&v0;
                xa[k][1] = *(ull*)&v1;
            }
#pragma unroll
            for (int h = 0; h < 16; h++) {
                F4U2 wv; wv.f = *(const float4*)(ws + h * CC + cb + c2p * 2);
#pragma unroll
                for (int k = 0; k < 2; k++) {
                    fma2(acc[h][k], wv.u[0], xa[k][0]);
                    fma2(acc[h][k], wv.u[1], xa[k][1]);
                }
            }
        }
        __syncwarp();
    }
#pragma unroll
    for (int h = 0; h < 16; h++) {
#pragma unroll
        for (int k = 0; k < 2; k++) {
            float2 p = *(float2*)&acc[h][k];
            d_logits[((size_t)b * HH + h) * NN + n0 + 32 * k + lane] = p.x + p.y;
        }
    }
}

// ---------------- K4: softmax over n per (b,h) ----------------
__global__ void softmax_kernel() {
    __shared__ float red[8];
    __shared__ float bcast;
    int r = blockIdx.x, tid = threadIdx.x;
    int lane = tid & 31, warp = tid >> 5;
    float* row = d_logits + (size_t)r * NN;
    float v[16];
#pragma unroll
    for (int i = 0; i < 16; i++) v[i] = row[tid + 256 * i];

    float m = -FLT_MAX;
#pragma unroll
    for (int i = 0; i < 16; i++) m = fmaxf(m, v[i]);
#pragma unroll
    for (int o = 16; o > 0; o >>= 1) m = fmaxf(m, __shfl_xor_sync(0xffffffffu, m, o));
    if (lane == 0) red[warp] = m;
    __syncthreads();
    if (tid == 0) {
        float t = red[0];
#pragma unroll
        for (int i = 1; i < 8; i++) t = fmaxf(t, red[i]);
        bcast = t;
    }
    __syncthreads();
    m = bcast;
    __syncthreads();

    float s = 0.f;
#pragma unroll
    for (int i = 0; i < 16; i++) { v[i] = __expf(v[i] - m); s += v[i]; }
#pragma unroll
    for (int o = 16; o > 0; o >>= 1) s += __shfl_xor_sync(0xffffffffu, s, o);
    if (lane == 0) red[warp] = s;
    __syncthreads();
    if (tid == 0) {
        float t = 0.f;
#pragma unroll
        for (int i = 0; i < 8; i++) t += red[i];
        bcast = t;
    }
    __syncthreads();
    float inv = 1.f / bcast;
#pragma unroll
    for (int i = 0; i < 16; i++) row[tid + 256 * i] = v[i] * inv;
}

// ---------------- K5: y-partials (f32x2, attn pre-duplicated) ----------------
// grid (32, 8), 256 threads; thread owns 4 channels (= 2 f32x2 lanes), acc[16][2].
__global__ __launch_bounds__(256) void ypart_kernel(const float* __restrict__ x) {
    __shared__ float2 as2[HH * 128];   // duplicated attn pairs (a,a), 16 KB
    int b = blockIdx.x, tile = blockIdx.y, tid = threadIdx.x;
    int c4 = tid * 4;
    ull acc[16][2];
#pragma unroll
    for (int h = 0; h < 16; h++) { acc[h][0] = 0ull; acc[h][1] = 0ull; }
    int n0 = tile * 512;

    for (int ch = 0; ch < 512; ch += 128) {
        // stage attn[16][128] for this chunk, duplicated into float2 pairs
#pragma unroll
        for (int j = 0; j < 2; j++) {
            int idx = tid + 256 * j;             // 0..511
            int h = idx >> 5, n4 = (idx & 31) * 4;
            float4 v = *(const float4*)(d_logits + ((size_t)b * HH + h) * NN + n0 + ch + n4);
            as2[h * 128 + n4 + 0] = make_float2(v.x, v.x);
            as2[h * 128 + n4 + 1] = make_float2(v.y, v.y);
            as2[h * 128 + n4 + 2] = make_float2(v.z, v.z);
            as2[h * 128 + n4 + 3] = make_float2(v.w, v.w);
        }
        __syncthreads();
        const float* xp = x + ((size_t)b * NN + n0 + ch) * CC + c4;
#pragma unroll 2
        for (int g = 0; g < 128; g += 4) {
            F4U2 xv0, xv1, xv2, xv3;
            xv0.f = *(const float4*)(xp + (size_t)(g + 0) * CC);
            xv1.f = *(const float4*)(xp + (size_t)(g + 1) * CC);
            xv2.f = *(const float4*)(xp + (size_t)(g + 2) * CC);
            xv3.f = *(const float4*)(xp + (size_t)(g + 3) * CC);
#pragma unroll
            for (int h = 0; h < 16; h++) {
                F4U2 a01, a23;
                a01.f = *(const float4*)&as2[h * 128 + g];
                a23.f = *(const float4*)&as2[h * 128 + g + 2];
                fma2(acc[h][0], a01.u[0], xv0.u[0]); fma2(acc[h][1], a01.u[0], xv0.u[1]);
                fma2(acc[h][0], a01.u[1], xv1.u[0]); fma2(acc[h][1], a01.u[1], xv1.u[1]);
                fma2(acc[h][0], a23.u[0], xv2.u[0]); fma2(acc[h][1], a23.u[0], xv2.u[1]);
                fma2(acc[h][0], a23.u[1], xv3.u[0]); fma2(acc[h][1], a23.u[1], xv3.u[1]);
            }
        }
        __syncthreads();
    }
#pragma unroll
    for (int h = 0; h < 16; h++) {
        F4U2 o; o.u[0] = acc[h][0]; o.u[1] = acc[h][1];
        *(float4*)(d_yp + (((size_t)tile * BB + b) * HH + h) * CC + c4) = o.f;
    }
}

// ---------------- K6: reduce partials, o = y@Wv, out = o@Wp + bp ----------------
__global__ void out_kernel(const float* __restrict__ Wv, const float* __restrict__ Wp,
                           const float* __restrict__ bp, float* __restrict__ out) {
    extern __shared__ float sm[];
    float* ys = sm;              // [16][1025]
    float* os = sm + 16 * 1025;  // [256]
    int b = blockIdx.x, tid = threadIdx.x;

    for (int i = tid; i < HH * CC; i += 256) {
        float s = 0.f;
#pragma unroll
        for (int t = 0; t < NTILES; t++)
            s += d_yp[((size_t)t * BB + b) * HH * CC + i];
        ys[(i >> 10) * 1025 + (i & 1023)] = s;
    }
    __syncthreads();

    int h = tid >> 4;
    float acc = 0.f;
#pragma unroll 8
    for (int c = 0; c < CC; c++)
        acc += ys[h * 1025 + c] * Wv[c * CRR + tid];
    os[tid] = acc;
    __syncthreads();

#pragma unroll
    for (int i = 0; i < 4; i++) {
        int j = tid + 256 * i;
        float a2 = bp[j];
#pragma unroll 8
        for (int r = 0; r < CRR; r++) a2 += os[r] * Wp[r * CC + j];
        out[(size_t)b * CC + j] = a2;
    }
}

// ---------------- launcher ----------------
extern "C" void kernel_launch(void* const* d_in, const int* in_sizes, int n_in,
                              void* d_out, int out_size) {
    const float* x  = (const float*)d_in[0];
    const float* Wq = (const float*)d_in[1];
    const float* Wk = (const float*)d_in[2];
    const float* Wv = (const float*)d_in[3];
    const float* Wp = (const float*)d_in[4];
    const float* bp = (const float*)d_in[5];
    float* out = (float*)d_out;

    const int smem_wk     = (64 * WKSTR + BB * CRR) * 4;             // ~97 KB
    const int smem_logits = HH * CC * 4 + 8 * (8 * XSTR) * 8;        // ~97 KB
    const int smem_out    = (16 * 1025 + 256) * 4;                   // ~65 KB

    cudaFuncSetAttribute(wk_kernel,     cudaFuncAttributeMaxDynamicSharedMemorySize, smem_wk);
    cudaFuncSetAttribute(logits_kernel, cudaFuncAttributeMaxDynamicSharedMemorySize, smem_logits);
    cudaFuncSetAttribute(out_kernel,    cudaFuncAttributeMaxDynamicSharedMemorySize, smem_out);

    qproj_kernel<<<BB, 256>>>(x, Wq);
    wk_kernel<<<16, 256, smem_wk>>>(Wk);
    logits_kernel<<<dim3(BB, 8), 256, smem_logits>>>(x);
    softmax_kernel<<<BB * HH, 256>>>();
    ypart_kernel<<<dim3(BB, NTILES), 256>>>(x);
    out_kernel<<<BB, 256, smem_out>>>(Wv, Wp, bp, out);
}

// round 13
// speedup vs baseline: 1.1007x; 1.1007x over previous
#include <cuda_runtime.h>
#include <math.h>
#include <float.h>

#define BB 32
#define NN 4096
#define CC 1024
#define CRR 256
#define HH 16
#define HDD 16
#define SCALE 0.25f
#define NTILES 8
#define WKSTR 260
#define TP 132      // K3 x-tile row stride (floats)
#define YP 20       // K5 attn tile row stride (floats)

// ---------------- device scratch ----------------
__device__ float  d_q[BB * CRR];
__device__ float  d_w[BB * CC * HH];        // [b][c][h] (heads contiguous)
__device__ float  d_logits[BB * HH * NN];
__device__ float2 d_ms[BB * HH];            // (rowmax, 1/sumexp)
__device__ float  d_yp[NTILES * BB * HH * CC];

// ---------------- K1: q[b,r] = (x[b,0,:] @ Wq[:,r]) * SCALE ----------------
__global__ void qproj_kernel(const float* __restrict__ x, const float* __restrict__ Wq) {
    __shared__ float x0[CC];
    int b = blockIdx.x, tid = threadIdx.x;
    const float* xb = x + (size_t)b * NN * CC;
    for (int i = tid; i < CC; i += 256) x0[i] = xb[i];
    __syncthreads();
    float acc = 0.f;
#pragma unroll 8
    for (int c = 0; c < CC; c++) acc += x0[c] * Wq[c * CRR + tid];
    d_q[b * CRR + tid] = acc * SCALE;
}

// ---------------- K2: w[b][c][h] = sum_d Wk[c, h*16+d] * q[b, h*16+d] ----------------
__global__ void wk_kernel(const float* __restrict__ Wk) {
    extern __shared__ float sm[];
    float* Wks = sm;                   // [64][WKSTR]
    float* qs  = sm + 64 * WKSTR;      // [32][256]
    int tid = threadIdx.x;
    int c0 = blockIdx.x * 64;
    for (int i = tid; i < 64 * 256; i += 256)
        Wks[(i >> 8) * WKSTR + (i & 255)] = Wk[c0 * 256 + i];
    for (int i = tid; i < BB * CRR; i += 256) qs[i] = d_q[i];
    __syncthreads();
    int rl = tid >> 2;          // local row 0..63
    int hg = tid & 3;           // head group 0..3
    for (int b = 0; b < BB; b++) {
#pragma unroll
        for (int k = 0; k < 4; k++) {
            int h = hg * 4 + k;
            float acc = 0.f;
#pragma unroll
            for (int d = 0; d < HDD; d++)
                acc += Wks[rl * WKSTR + h * 16 + d] * qs[b * 256 + h * 16 + d];
            d_w[((size_t)b * CC + c0 + rl) * HH + h] = acc;
        }
    }
}

// ---------------- nop (launch-slot shim so ncu capture lands on logits) --------
__global__ void nop_kernel() {}

// ---------------- K3: logits[b,h,n] = x[b,n,:] . w[b,h,:] ----------------
// block 128 thr = 4 warps; warp owns 128 tokens (4 consecutive / lane).
// grid (32, 8). smem: ws[1024][16] (64KB) + per-warp double-buffered x tile
// [8 chans][TP] x2 (~8.3KB/warp). Per chan step: 1 LDS.128 (x, conflict-free)
// + 4 LDS.128 (w, broadcast) -> 64 FFMA. FMA-bound by construction.
__global__ __launch_bounds__(128, 2) void logits_kernel(const float* __restrict__ x) {
    extern __shared__ float sm[];
    float* ws = sm;                                  // [1024][16]
    int tid = threadIdx.x, lane = tid & 31, warp = tid >> 5;
    float* xbuf = sm + CC * HH + warp * (2 * 8 * TP);
    int b = blockIdx.x;

    const float4* wsrc = (const float4*)(d_w + (size_t)b * CC * HH);
    float4* wdst = (float4*)ws;
#pragma unroll 4
    for (int i = tid; i < (CC * HH) / 4; i += 128) wdst[i] = wsrc[i];
    __syncthreads();

    int n0 = blockIdx.y * 512 + warp * 128;
    const float* xg = x + ((size_t)b * NN + n0) * CC;

    float acc[4][16];
#pragma unroll
    for (int t = 0; t < 4; t++)
#pragma unroll
        for (int h = 0; h < 16; h++) acc[t][h] = 0.f;

    float4 pf[8];
    // prologue: load + store group 0
#pragma unroll
    for (int i = 0; i < 8; i++) {
        int lin = lane + 32 * i; int t = lin >> 1; int c4 = (lin & 1) * 4;
        pf[i] = *(const float4*)(xg + (size_t)t * CC + c4);
    }
    {
        float* bw = xbuf;
#pragma unroll
        for (int i = 0; i < 8; i++) {
            int lin = lane + 32 * i; int t = lin >> 1; int c4 = (lin & 1) * 4;
            bw[(c4 + 0) * TP + t] = pf[i].x;
            bw[(c4 + 1) * TP + t] = pf[i].y;
            bw[(c4 + 2) * TP + t] = pf[i].z;
            bw[(c4 + 3) * TP + t] = pf[i].w;
        }
    }
    __syncwarp();

    int cur = 0;
    for (int g = 0; g < 128; g++) {
        if (g < 127) {
            int cb2 = (g + 1) * 8;
#pragma unroll
            for (int i = 0; i < 8; i++) {
                int lin = lane + 32 * i; int t = lin >> 1; int c4 = (lin & 1) * 4;
                pf[i] = *(const float4*)(xg + (size_t)t * CC + cb2 + c4);
            }
        }
        const float* br = xbuf + cur * 8 * TP;
        int cb = g * 8;
#pragma unroll
        for (int c = 0; c < 8; c++) {
            float4 xv = *(const float4*)&br[c * TP + lane * 4];
            const float* wr = ws + (cb + c) * 16;
            float4 w0 = *(const float4*)(wr);
            float4 w1 = *(const float4*)(wr + 4);
            float4 w2 = *(const float4*)(wr + 8);
            float4 w3 = *(const float4*)(wr + 12);
            float xt[4] = {xv.x, xv.y, xv.z, xv.w};
#pragma unroll
            for (int t = 0; t < 4; t++) {
                acc[t][0]  += xt[t] * w0.x; acc[t][1]  += xt[t] * w0.y;
                acc[t][2]  += xt[t] * w0.z; acc[t][3]  += xt[t] * w0.w;
                acc[t][4]  += xt[t] * w1.x; acc[t][5]  += xt[t] * w1.y;
                acc[t][6]  += xt[t] * w1.z; acc[t][7]  += xt[t] * w1.w;
                acc[t][8]  += xt[t] * w2.x; acc[t][9]  += xt[t] * w2.y;
                acc[t][10] += xt[t] * w2.z; acc[t][11] += xt[t] * w2.w;
                acc[t][12] += xt[t] * w3.x; acc[t][13] += xt[t] * w3.y;
                acc[t][14] += xt[t] * w3.z; acc[t][15] += xt[t] * w3.w;
            }
        }
        if (g < 127) {
            float* bw = xbuf + (1 - cur) * 8 * TP;
#pragma unroll
            for (int i = 0; i < 8; i++) {
                int lin = lane + 32 * i; int t = lin >> 1; int c4 = (lin & 1) * 4;
                bw[(c4 + 0) * TP + t] = pf[i].x;
                bw[(c4 + 1) * TP + t] = pf[i].y;
                bw[(c4 + 2) * TP + t] = pf[i].z;
                bw[(c4 + 3) * TP + t] = pf[i].w;
            }
            __syncwarp();
            cur ^= 1;
        }
    }
    int nbase = n0 + lane * 4;
#pragma unroll
    for (int h = 0; h < 16; h++) {
        float4 o = make_float4(acc[0][h], acc[1][h], acc[2][h], acc[3][h]);
        *(float4*)(d_logits + ((size_t)b * HH + h) * NN + nbase) = o;
    }
}

// ---------------- K4: row stats (max, 1/sumexp) per (b,h) ----------------
__global__ void stats_kernel() {
    __shared__ float red[8];
    __shared__ float bc;
    int r = blockIdx.x, tid = threadIdx.x;
    int lane = tid & 31, warp = tid >> 5;
    const float* row = d_logits + (size_t)r * NN;
    float v[16];
#pragma unroll
    for (int i = 0; i < 16; i++) v[i] = row[tid + 256 * i];

    float m = -FLT_MAX;
#pragma unroll
    for (int i = 0; i < 16; i++) m = fmaxf(m, v[i]);
#pragma unroll
    for (int o = 16; o > 0; o >>= 1) m = fmaxf(m, __shfl_xor_sync(0xffffffffu, m, o));
    if (lane == 0) red[warp] = m;
    __syncthreads();
    if (tid == 0) {
        float t = red[0];
#pragma unroll
        for (int i = 1; i < 8; i++) t = fmaxf(t, red[i]);
        bc = t;
    }
    __syncthreads();
    m = bc;
    __syncthreads();

    float s = 0.f;
#pragma unroll
    for (int i = 0; i < 16; i++) s += __expf(v[i] - m);
#pragma unroll
    for (int o = 16; o > 0; o >>= 1) s += __shfl_xor_sync(0xffffffffu, s, o);
    if (lane == 0) red[warp] = s;
    __syncthreads();
    if (tid == 0) {
        float t = 0.f;
#pragma unroll
        for (int i = 0; i < 8; i++) t += red[i];
        d_ms[r] = make_float2(m, 1.f / t);
    }
}

// ---------------- K5: y-partials with softmax applied on the fly ----------------
// grid (32, 8), 256 thr; thread owns 4 chans (c4 = tid*4), acc float4[16].
// Per token: 1 coalesced LDG.128 (x) + 4 broadcast LDS.128 (attn) -> 64 FFMA.
__global__ __launch_bounds__(256, 2) void ypart_kernel(const float* __restrict__ x) {
    __shared__ float as[128 * YP];     // attn chunk, transposed [n][h] padded
    int b = blockIdx.x, tile = blockIdx.y, tid = threadIdx.x;
    int c4 = tid * 4;
    float4 acc[16];
#pragma unroll
    for (int h = 0; h < 16; h++) acc[h] = make_float4(0.f, 0.f, 0.f, 0.f);
    int n0 = tile * 512;

    for (int ch = 0; ch < 512; ch += 128) {
        {   // stage attn for this 128-token chunk: thread -> (h, 8 tokens)
            int h = tid >> 4, nb = (tid & 15) * 8;
            float2 ms = d_ms[b * HH + h];
            const float* lp = d_logits + ((size_t)b * HH + h) * NN + n0 + ch + nb;
#pragma unroll
            for (int j = 0; j < 8; j++)
                as[(nb + j) * YP + h] = __expf(lp[j] - ms.x) * ms.y;
        }
        __syncthreads();
        const float* xp = x + ((size_t)b * NN + n0 + ch) * CC + c4;
#pragma unroll 2
        for (int n = 0; n < 128; n++) {
            float4 xv = *(const float4*)(xp + (size_t)n * CC);
            float4 a0 = *(const float4*)&as[n * YP];
            float4 a1 = *(const float4*)&as[n * YP + 4];
            float4 a2 = *(const float4*)&as[n * YP + 8];
            float4 a3 = *(const float4*)&as[n * YP + 12];
            acc[0].x  += a0.x * xv.x; acc[0].y  += a0.x * xv.y; acc[0].z  += a0.x * xv.z; acc[0].w  += a0.x * xv.w;
            acc[1].x  += a0.y * xv.x; acc[1].y  += a0.y * xv.y; acc[1].z  += a0.y * xv.z; acc[1].w  += a0.y * xv.w;
            acc[2].x  += a0.z * xv.x; acc[2].y  += a0.z * xv.y; acc[2].z  += a0.z * xv.z; acc[2].w  += a0.z * xv.w;
            acc[3].x  += a0.w * xv.x; acc[3].y  += a0.w * xv.y; acc[3].z  += a0.w * xv.z; acc[3].w  += a0.w * xv.w;
            acc[4].x  += a1.x * xv.x; acc[4].y  += a1.x * xv.y; acc[4].z  += a1.x * xv.z; acc[4].w  += a1.x * xv.w;
            acc[5].x  += a1.y * xv.x; acc[5].y  += a1.y * xv.y; acc[5].z  += a1.y * xv.z; acc[5].w  += a1.y * xv.w;
            acc[6].x  += a1.z * xv.x; acc[6].y  += a1.z * xv.y; acc[6].z  += a1.z * xv.z; acc[6].w  += a1.z * xv.w;
            acc[7].x  += a1.w * xv.x; acc[7].y  += a1.w * xv.y; acc[7].z  += a1.w * xv.z; acc[7].w  += a1.w * xv.w;
            acc[8].x  += a2.x * xv.x; acc[8].y  += a2.x * xv.y; acc[8].z  += a2.x * xv.z; acc[8].w  += a2.x * xv.w;
            acc[9].x  += a2.y * xv.x; acc[9].y  += a2.y * xv.y; acc[9].z  += a2.y * xv.z; acc[9].w  += a2.y * xv.w;
            acc[10].x += a2.z * xv.x; acc[10].y += a2.z * xv.y; acc[10].z += a2.z * xv.z; acc[10].w += a2.z * xv.w;
            acc[11].x += a2.w * xv.x; acc[11].y += a2.w * xv.y; acc[11].z += a2.w * xv.z; acc[11].w += a2.w * xv.w;
            acc[12].x += a3.x * xv.x; acc[12].y += a3.x * xv.y; acc[12].z += a3.x * xv.z; acc[12].w += a3.x * xv.w;
            acc[13].x += a3.y * xv.x; acc[13].y += a3.y * xv.y; acc[13].z += a3.y * xv.z; acc[13].w += a3.y * xv.w;
            acc[14].x += a3.z * xv.x; acc[14].y += a3.z * xv.y; acc[14].z += a3.z * xv.z; acc[14].w += a3.z * xv.w;
            acc[15].x += a3.w * xv.x; acc[15].y += a3.w * xv.y; acc[15].z += a3.w * xv.z; acc[15].w += a3.w * xv.w;
        }
        __syncthreads();
    }
#pragma unroll
    for (int h = 0; h < 16; h++)
        *(float4*)(d_yp + (((size_t)tile * BB + b) * HH + h) * CC + c4) = acc[h];
}

// ---------------- K6: reduce partials, o = y@Wv, out = o@Wp + bp ----------------
__global__ void out_kernel(const float* __restrict__ Wv, const float* __restrict__ Wp,
                           const float* __restrict__ bp, float* __restrict__ out) {
    extern __shared__ float sm[];
    float* ys = sm;              // [16][1025]
    float* os = sm + 16 * 1025;  // [256]
    int b = blockIdx.x, tid = threadIdx.x;

    for (int i = tid; i < HH * CC; i += 256) {
        float s = 0.f;
#pragma unroll
        for (int t = 0; t < NTILES; t++)
            s += d_yp[((size_t)t * BB + b) * HH * CC + i];
        ys[(i >> 10) * 1025 + (i & 1023)] = s;
    }
    __syncthreads();

    int h = tid >> 4;
    float acc = 0.f;
#pragma unroll 8
    for (int c = 0; c < CC; c++)
        acc += ys[h * 1025 + c] * Wv[c * CRR + tid];
    os[tid] = acc;
    __syncthreads();

#pragma unroll
    for (int i = 0; i < 4; i++) {
        int j = tid + 256 * i;
        float a2 = bp[j];
#pragma unroll 8
        for (int r = 0; r < CRR; r++) a2 += os[r] * Wp[r * CC + j];
        out[(size_t)b * CC + j] = a2;
    }
}

// ---------------- launcher ----------------
extern "C" void kernel_launch(void* const* d_in, const int* in_sizes, int n_in,
                              void* d_out, int out_size) {
    const float* x  = (const float*)d_in[0];
    const float* Wq = (const float*)d_in[1];
    const float* Wk = (const float*)d_in[2];
    const float* Wv = (const float*)d_in[3];
    const float* Wp = (const float*)d_in[4];
    const float* bp = (const float*)d_in[5];
    float* out = (float*)d_out;

    const int smem_wk     = (64 * WKSTR + BB * CRR) * 4;        // ~97 KB
    const int smem_logits = CC * HH * 4 + 4 * (2 * 8 * TP) * 4; // 64KB + 33KB
    const int smem_out    = (16 * 1025 + 256) * 4;              // ~65 KB

    cudaFuncSetAttribute(wk_kernel,     cudaFuncAttributeMaxDynamicSharedMemorySize, smem_wk);
    cudaFuncSetAttribute(logits_kernel, cudaFuncAttributeMaxDynamicSharedMemorySize, smem_logits);
    cudaFuncSetAttribute(out_kernel,    cudaFuncAttributeMaxDynamicSharedMemorySize, smem_out);

    qproj_kernel<<<BB, 256>>>(x, Wq);                    // 1
    wk_kernel<<<16, 256, smem_wk>>>(Wk);                 // 2
    nop_kernel<<<1, 32>>>();                             // 3 (capture shim)
    logits_kernel<<<dim3(BB, 8), 128, smem_logits>>>(x); // 4  <- big pass 1
    stats_kernel<<<BB * HH, 256>>>();                    // 5
    ypart_kernel<<<dim3(BB, NTILES), 256>>>(x);          // 6  <- big pass 2
    out_kernel<<<BB, 256, smem_out>>>(Wv, Wp, bp, out);  // 7
}